// round 6
// baseline (speedup 1.0000x reference)
#include <cuda_runtime.h>

typedef unsigned long long ull;

// ---- f32x2 packed helpers (Blackwell) ----
__device__ __forceinline__ ull ffma2(ull a, ull b, ull c) {
    ull d;
    asm("fma.rn.f32x2 %0, %1, %2, %3;" : "=l"(d) : "l"(a), "l"(b), "l"(c));
    return d;
}
__device__ __forceinline__ ull pack2(float lo, float hi) {
    ull r;
    asm("mov.b64 %0, {%1, %2};" : "=l"(r) : "f"(lo), "f"(hi));
    return r;
}
__device__ __forceinline__ void unpack2(ull v, float& lo, float& hi) {
    asm("mov.b64 {%0, %1}, %2;" : "=f"(lo), "=f"(hi) : "l"(v));
}

static constexpr int THREADS = 256;
static constexpr int R = 2;                 // rows per thread
static constexpr int TILE = THREADS * R;    // 512 rows per CTA

// SMEM layout (float offsets). XS holds 32 of the 64 features at a time (2-phase).
// All strides chosen 16B-aligned with odd 16B-unit stride -> conflict-free v4 loads.
static constexpr int XS_STRIDE = 36;   // 36*4B=144B, 9 x 16B (odd) -> conflict-free
static constexpr int W1_STRIDE = 36;   // quads of output-pairs 16B aligned
static constexpr int W2_STRIDE = 20;   // 5 x 16B (odd)
static constexpr int OFF_XS  = 0;                          // 512*36 = 18432
static constexpr int OFF_WT1 = OFF_XS + TILE * XS_STRIDE;  // 18432 : 64*36 = 2304
static constexpr int OFF_WT2 = OFF_WT1 + 64 * W1_STRIDE;   // 20736 : 32*20 = 640
static constexpr int OFF_W3  = OFF_WT2 + 32 * W2_STRIDE;   // 21376 : 16 (16B aligned)
static constexpr int OFF_B1  = OFF_W3 + 16;                // 21392 : 32
static constexpr int OFF_B2  = OFF_B1 + 32;                // 21424 : 16
static constexpr int SMEM_FLOATS = OFF_B2 + 16;            // 21440
static constexpr int SMEM_BYTES  = SMEM_FLOATS * 4;        // 85760 -> 2 CTAs/SM

__global__ void __launch_bounds__(THREADS, 2)
hybridq_kernel(const float* __restrict__ x_q,
               const float* __restrict__ x_c,
               const float* __restrict__ q_params,
               const float* __restrict__ w1,
               const float* __restrict__ b1,
               const float* __restrict__ w2,
               const float* __restrict__ b2,
               const float* __restrict__ w3,
               const float* __restrict__ b3,
               float* __restrict__ out,
               int B)
{
    extern __shared__ float sm[];
    float* XS  = sm + OFF_XS;
    float* WT1 = sm + OFF_WT1;
    float* WT2 = sm + OFF_WT2;
    float* W3S = sm + OFF_W3;
    float* B1S = sm + OFF_B1;
    float* B2S = sm + OFF_B2;

    const int tid = threadIdx.x;
    const int r0  = blockIdx.x * TILE;
    const int rows = min(TILE, B - r0);

    // ---- stage weights transposed; WT1[k][t], WT2[j][m] ----
    #pragma unroll
    for (int i = 0; i < 8; ++i) {
        int idx = tid + 256 * i;                 // w1 is [32][64]
        int t = idx >> 6, k = idx & 63;
        WT1[k * W1_STRIDE + t] = w1[idx];
    }
    #pragma unroll
    for (int i = 0; i < 2; ++i) {
        int idx = tid + 256 * i;                 // w2 is [16][32]
        int m = idx >> 5, j = idx & 31;
        WT2[j * W2_STRIDE + m] = w2[idx];
    }
    if (tid < 16) W3S[tid] = w3[tid];
    if (tid < 32) B1S[tid] = b1[tid];
    if (tid < 16) B2S[tid] = b2[tid];

    // ---- q_out (closed-form circuit) into XS col 0; balanced across threads ----
    {
        const float qp1 = __ldg(q_params + 1);
        const float qp2 = __ldg(q_params + 2);
        #pragma unroll
        for (int r = 0; r < R; ++r) {
            int row = tid + 256 * r;
            if (row < rows) {
                long long g = (long long)(r0 + row) * 3;
                XS[row * XS_STRIDE] =
                    __cosf(x_q[g + 1] + qp1) * __cosf(x_q[g + 2] + qp2);
            }
        }
    }

    // ---- phase A staging: combined cols 1..31 = x_c cols 0..30 ----
    // i = tid + 256*it: within a warp, c=i&31 spans 0..31, row fixed -> coalesced LDG,
    // conflict-free consecutive STS.
    #pragma unroll
    for (int it = 0; it < 64; ++it) {
        int i = tid + 256 * it;
        int c = i & 31, row = i >> 5;
        if (c && row < rows)
            XS[row * XS_STRIDE + c] = x_c[(long long)(r0 + row) * 63 + (c - 1)];
    }
    __syncthreads();

    const int xb0 = tid * XS_STRIDE;
    const int xb1 = (tid + 256) * XS_STRIDE;

    // acc[r][p] = output pair (2p, 2p+1) of layer 1
    ull acc[R][16];
    #pragma unroll
    for (int p = 0; p < 16; ++p) {
        const ull bp = *reinterpret_cast<const ull*>(B1S + 2 * p);
        acc[0][p] = bp; acc[1][p] = bp;
    }

    // ---- phase A compute: features 0..31 ----
    #pragma unroll 4
    for (int c = 0; c < 8; ++c) {
        const float4 va = *reinterpret_cast<const float4*>(XS + xb0 + 4 * c);
        const float4 vb = *reinterpret_cast<const float4*>(XS + xb1 + 4 * c);
        const float ea[4] = {va.x, va.y, va.z, va.w};
        const float eb[4] = {vb.x, vb.y, vb.z, vb.w};
        #pragma unroll
        for (int e = 0; e < 4; ++e) {
            const ull xx0 = pack2(ea[e], ea[e]);
            const ull xx1 = pack2(eb[e], eb[e]);
            const float* wf = WT1 + (4 * c + e) * W1_STRIDE;
            #pragma unroll
            for (int q = 0; q < 8; ++q) {
                const ulonglong2 wv = *reinterpret_cast<const ulonglong2*>(wf + 4 * q);
                acc[0][2 * q]     = ffma2(wv.x, xx0, acc[0][2 * q]);
                acc[1][2 * q]     = ffma2(wv.x, xx1, acc[1][2 * q]);
                acc[0][2 * q + 1] = ffma2(wv.y, xx0, acc[0][2 * q + 1]);
                acc[1][2 * q + 1] = ffma2(wv.y, xx1, acc[1][2 * q + 1]);
            }
        }
    }

    // ---- phase B staging: combined cols 32..63 = x_c cols 31..62 ----
    __syncthreads();
    #pragma unroll
    for (int it = 0; it < 64; ++it) {
        int i = tid + 256 * it;
        int c = i & 31, row = i >> 5;
        if (row < rows)
            XS[row * XS_STRIDE + c] = x_c[(long long)(r0 + row) * 63 + 31 + c];
    }
    __syncthreads();

    // ---- phase B compute: features 32..63 ----
    #pragma unroll 4
    for (int c = 0; c < 8; ++c) {
        const float4 va = *reinterpret_cast<const float4*>(XS + xb0 + 4 * c);
        const float4 vb = *reinterpret_cast<const float4*>(XS + xb1 + 4 * c);
        const float ea[4] = {va.x, va.y, va.z, va.w};
        const float eb[4] = {vb.x, vb.y, vb.z, vb.w};
        #pragma unroll
        for (int e = 0; e < 4; ++e) {
            const ull xx0 = pack2(ea[e], ea[e]);
            const ull xx1 = pack2(eb[e], eb[e]);
            const float* wf = WT1 + (32 + 4 * c + e) * W1_STRIDE;
            #pragma unroll
            for (int q = 0; q < 8; ++q) {
                const ulonglong2 wv = *reinterpret_cast<const ulonglong2*>(wf + 4 * q);
                acc[0][2 * q]     = ffma2(wv.x, xx0, acc[0][2 * q]);
                acc[1][2 * q]     = ffma2(wv.x, xx1, acc[1][2 * q]);
                acc[0][2 * q + 1] = ffma2(wv.y, xx0, acc[0][2 * q + 1]);
                acc[1][2 * q + 1] = ffma2(wv.y, xx1, acc[1][2 * q + 1]);
            }
        }
    }

    // relu -> h1
    float h1[R][32];
    #pragma unroll
    for (int r = 0; r < R; ++r)
        #pragma unroll
        for (int p = 0; p < 16; ++p) {
            float lo, hi;
            unpack2(acc[r][p], lo, hi);
            h1[r][2 * p]     = fmaxf(lo, 0.0f);
            h1[r][2 * p + 1] = fmaxf(hi, 0.0f);
        }

    // ================= layer 2: h2[16] = relu(W2 @ h1 + b2) =================
    ull a2[R][8];
    #pragma unroll
    for (int p = 0; p < 8; ++p) {
        const ull bp = *reinterpret_cast<const ull*>(B2S + 2 * p);
        a2[0][p] = bp; a2[1][p] = bp;
    }
    #pragma unroll
    for (int j = 0; j < 32; ++j) {
        const float* w2r = WT2 + j * W2_STRIDE;
        const ull xx0 = pack2(h1[0][j], h1[0][j]);
        const ull xx1 = pack2(h1[1][j], h1[1][j]);
        #pragma unroll
        for (int q = 0; q < 4; ++q) {
            const ulonglong2 wv = *reinterpret_cast<const ulonglong2*>(w2r + 4 * q);
            a2[0][2 * q]     = ffma2(wv.x, xx0, a2[0][2 * q]);
            a2[1][2 * q]     = ffma2(wv.x, xx1, a2[1][2 * q]);
            a2[0][2 * q + 1] = ffma2(wv.y, xx0, a2[0][2 * q + 1]);
            a2[1][2 * q + 1] = ffma2(wv.y, xx1, a2[1][2 * q + 1]);
        }
    }

    float h2[R][16];
    #pragma unroll
    for (int r = 0; r < R; ++r)
        #pragma unroll
        for (int p = 0; p < 8; ++p) {
            float lo, hi;
            unpack2(a2[r][p], lo, hi);
            h2[r][2 * p]     = fmaxf(lo, 0.0f);
            h2[r][2 * p + 1] = fmaxf(hi, 0.0f);
        }

    // ================= layer 3: out = w3 . h2 + b3 =================
    const float b3v = __ldg(b3);
    #pragma unroll
    for (int r = 0; r < R; ++r) {
        ull a3 = pack2(b3v, 0.0f);
        #pragma unroll
        for (int v = 0; v < 4; ++v) {
            const ulonglong2 wv = *reinterpret_cast<const ulonglong2*>(W3S + 4 * v);
            a3 = ffma2(wv.x, pack2(h2[r][4 * v],     h2[r][4 * v + 1]), a3);
            a3 = ffma2(wv.y, pack2(h2[r][4 * v + 2], h2[r][4 * v + 3]), a3);
        }
        float lo, hi;
        unpack2(a3, lo, hi);
        int row = tid + 256 * r;
        if (row < rows) out[r0 + row] = lo + hi;
    }
}

extern "C" void kernel_launch(void* const* d_in, const int* in_sizes, int n_in,
                              void* d_out, int out_size)
{
    const float* x_q      = (const float*)d_in[0];
    const float* x_c      = (const float*)d_in[1];
    const float* q_params = (const float*)d_in[2];
    const float* w1       = (const float*)d_in[3];
    const float* b1       = (const float*)d_in[4];
    const float* w2       = (const float*)d_in[5];
    const float* b2       = (const float*)d_in[6];
    const float* w3       = (const float*)d_in[7];
    const float* b3       = (const float*)d_in[8];
    float* out            = (float*)d_out;

    const int B = in_sizes[0] / 3;
    const int blocks = (B + TILE - 1) / TILE;

    cudaFuncSetAttribute(hybridq_kernel,
                         cudaFuncAttributeMaxDynamicSharedMemorySize, SMEM_BYTES);

    hybridq_kernel<<<blocks, THREADS, SMEM_BYTES>>>(
        x_q, x_c, q_params, w1, b1, w2, b2, w3, b3, out, B);
}

// round 8
// speedup vs baseline: 2.2322x; 2.2322x over previous
#include <cuda_runtime.h>

typedef unsigned long long ull;
typedef unsigned int u32;

// ---- f32x2 packed helpers (Blackwell) ----
__device__ __forceinline__ ull ffma2(ull a, ull b, ull c) {
    ull d;
    asm("fma.rn.f32x2 %0, %1, %2, %3;" : "=l"(d) : "l"(a), "l"(b), "l"(c));
    return d;
}
__device__ __forceinline__ ull pack2(float lo, float hi) {
    ull r;
    asm("mov.b64 %0, {%1, %2};" : "=l"(r) : "f"(lo), "f"(hi));
    return r;
}
__device__ __forceinline__ void unpack2(ull v, float& lo, float& hi) {
    asm("mov.b64 {%0, %1}, %2;" : "=f"(lo), "=f"(hi) : "l"(v));
}
__device__ __forceinline__ u32 smem_u32(const void* p) {
    u32 a;
    asm("{ .reg .u64 t; cvta.to.shared.u64 t, %1; cvt.u32.u64 %0, t; }" : "=r"(a) : "l"(p));
    return a;
}
__device__ __forceinline__ void cp_async16(u32 saddr, const void* gaddr) {
    asm volatile("cp.async.cg.shared.global [%0], [%1], 16;" :: "r"(saddr), "l"(gaddr));
}

static constexpr int THREADS = 384;         // 12 warps -> 3 warps/SMSP
static constexpr int R = 2;                 // rows per thread
static constexpr int TILE = THREADS * R;    // 768 rows per CTA

// SMEM layout (float offsets); all 16B-aligned regions.
static constexpr int W1_STRIDE = 36;        // 36 floats = 144B = 9 x 16B (odd) per feature row
static constexpr int W2_STRIDE = 20;        // 80B = 5 x 16B (odd)
static constexpr int OFF_XS  = 0;                          // verbatim [768][63] = 48384
static constexpr int OFF_Q   = OFF_XS + TILE * 63;         // 48384 : 768
static constexpr int OFF_WT1 = OFF_Q + TILE;               // 49152 : 64*36 = 2304
static constexpr int OFF_WT2 = OFF_WT1 + 64 * W1_STRIDE;   // 51456 : 32*20 = 640
static constexpr int OFF_W3  = OFF_WT2 + 32 * W2_STRIDE;   // 52096 : 16
static constexpr int OFF_B1  = OFF_W3 + 16;                // 52112 : 32
static constexpr int OFF_B2  = OFF_B1 + 32;                // 52144 : 16
static constexpr int SMEM_FLOATS = OFF_B2 + 16;            // 52160
static constexpr int SMEM_BYTES  = SMEM_FLOATS * 4;        // 208640 -> 1 CTA/SM

__global__ void __launch_bounds__(THREADS, 1)
hybridq_kernel(const float* __restrict__ x_q,
               const float* __restrict__ x_c,
               const float* __restrict__ q_params,
               const float* __restrict__ w1,
               const float* __restrict__ b1,
               const float* __restrict__ w2,
               const float* __restrict__ b2,
               const float* __restrict__ w3,
               const float* __restrict__ b3,
               float* __restrict__ out,
               int B)
{
    extern __shared__ float sm[];
    float* XS  = sm + OFF_XS;
    float* Q   = sm + OFF_Q;
    float* WT1 = sm + OFF_WT1;
    float* WT2 = sm + OFF_WT2;
    float* W3S = sm + OFF_W3;
    float* B1S = sm + OFF_B1;
    float* B2S = sm + OFF_B2;

    const int tid = threadIdx.x;
    const int r0  = blockIdx.x * TILE;
    const int rows = min(TILE, B - r0);

    // ---- async stage of x_c tile: verbatim contiguous copy, 16B chunks ----
    {
        const u32 s_xs = smem_u32(XS);
        const float* src = x_c + (long long)r0 * 63;
        const int chunks = (rows * 63) >> 2;          // rows*63 is divisible by 4
        for (int i = tid; i < chunks; i += THREADS)
            cp_async16(s_xs + (u32)i * 16u, src + 4 * i);
        asm volatile("cp.async.commit_group;");
    }

    // ---- stage weights transposed while cp.async flies ----
    #pragma unroll
    for (int i = 0; i < 6; ++i) {
        int idx = tid + THREADS * i;            // w1 is [32][64], 2048 elems
        if (idx < 2048) {
            int t = idx >> 6, k = idx & 63;
            WT1[k * W1_STRIDE + t] = w1[idx];
        }
    }
    #pragma unroll
    for (int i = 0; i < 2; ++i) {
        int idx = tid + THREADS * i;            // w2 is [16][32], 512 elems
        if (idx < 512) {
            int m = idx >> 5, j = idx & 31;
            WT2[j * W2_STRIDE + m] = w2[idx];
        }
    }
    if (tid < 16) W3S[tid] = w3[tid];
    if (tid < 32) B1S[tid] = b1[tid];
    if (tid < 16) B2S[tid] = b2[tid];

    // ---- q_out column (closed-form circuit: cos(x1+w1)*cos(x2+w2)) ----
    {
        const float qp1 = __ldg(q_params + 1);
        const float qp2 = __ldg(q_params + 2);
        #pragma unroll
        for (int r = 0; r < R; ++r) {
            int row = tid + THREADS * r;
            if (row < rows) {
                long long g = (long long)(r0 + row) * 3;
                Q[row] = __cosf(x_q[g + 1] + qp1) * __cosf(x_q[g + 2] + qp2);
            }
        }
    }

    asm volatile("cp.async.wait_group 0;");
    __syncthreads();

    const int xb0 = tid * 63;
    const int xb1 = (tid + THREADS) * 63;

    // ================= layer 1: h1[32] = relu(W1 @ [q,x] + b1) =================
    // acc[r][p] holds outputs (2p, 2p+1) in the two f32 lanes.
    ull acc[R][16];
    #pragma unroll
    for (int p = 0; p < 16; ++p) {
        const ull bp = *reinterpret_cast<const ull*>(B1S + 2 * p);
        acc[0][p] = bp; acc[1][p] = bp;
    }

    // feature 0 : q_out
    {
        const float q0 = Q[tid];
        const float q1 = Q[tid + THREADS];
        const ull xx0 = pack2(q0, q0);
        const ull xx1 = pack2(q1, q1);
        #pragma unroll
        for (int qd = 0; qd < 8; ++qd) {
            const ulonglong2 wv = *reinterpret_cast<const ulonglong2*>(WT1 + 4 * qd);
            acc[0][2 * qd]     = ffma2(wv.x, xx0, acc[0][2 * qd]);
            acc[1][2 * qd]     = ffma2(wv.x, xx1, acc[1][2 * qd]);
            acc[0][2 * qd + 1] = ffma2(wv.y, xx0, acc[0][2 * qd + 1]);
            acc[1][2 * qd + 1] = ffma2(wv.y, xx1, acc[1][2 * qd + 1]);
        }
    }

    // features 1..63 : x_c cols 0..62 (stride-63 rows -> conflict-free LDS.32)
    #pragma unroll 9
    for (int k = 0; k < 63; ++k) {
        const float x0 = XS[xb0 + k];
        const float x1 = XS[xb1 + k];
        const ull xx0 = pack2(x0, x0);
        const ull xx1 = pack2(x1, x1);
        const float* wf = WT1 + (k + 1) * W1_STRIDE;
        #pragma unroll
        for (int qd = 0; qd < 8; ++qd) {
            const ulonglong2 wv = *reinterpret_cast<const ulonglong2*>(wf + 4 * qd);
            acc[0][2 * qd]     = ffma2(wv.x, xx0, acc[0][2 * qd]);
            acc[1][2 * qd]     = ffma2(wv.x, xx1, acc[1][2 * qd]);
            acc[0][2 * qd + 1] = ffma2(wv.y, xx0, acc[0][2 * qd + 1]);
            acc[1][2 * qd + 1] = ffma2(wv.y, xx1, acc[1][2 * qd + 1]);
        }
    }

    // relu -> h1
    float h1[R][32];
    #pragma unroll
    for (int r = 0; r < R; ++r)
        #pragma unroll
        for (int p = 0; p < 16; ++p) {
            float lo, hi;
            unpack2(acc[r][p], lo, hi);
            h1[r][2 * p]     = fmaxf(lo, 0.0f);
            h1[r][2 * p + 1] = fmaxf(hi, 0.0f);
        }

    // ================= layer 2: h2[16] = relu(W2 @ h1 + b2) =================
    ull a2[R][8];
    #pragma unroll
    for (int p = 0; p < 8; ++p) {
        const ull bp = *reinterpret_cast<const ull*>(B2S + 2 * p);
        a2[0][p] = bp; a2[1][p] = bp;
    }
    #pragma unroll
    for (int j = 0; j < 32; ++j) {
        const float* w2r = WT2 + j * W2_STRIDE;
        const ull xx0 = pack2(h1[0][j], h1[0][j]);
        const ull xx1 = pack2(h1[1][j], h1[1][j]);
        #pragma unroll
        for (int v = 0; v < 4; ++v) {
            const ulonglong2 wv = *reinterpret_cast<const ulonglong2*>(w2r + 4 * v);
            a2[0][2 * v]     = ffma2(wv.x, xx0, a2[0][2 * v]);
            a2[1][2 * v]     = ffma2(wv.x, xx1, a2[1][2 * v]);
            a2[0][2 * v + 1] = ffma2(wv.y, xx0, a2[0][2 * v + 1]);
            a2[1][2 * v + 1] = ffma2(wv.y, xx1, a2[1][2 * v + 1]);
        }
    }

    float h2[R][16];
    #pragma unroll
    for (int r = 0; r < R; ++r)
        #pragma unroll
        for (int p = 0; p < 8; ++p) {
            float lo, hi;
            unpack2(a2[r][p], lo, hi);
            h2[r][2 * p]     = fmaxf(lo, 0.0f);
            h2[r][2 * p + 1] = fmaxf(hi, 0.0f);
        }

    // ================= layer 3: out = w3 . h2 + b3 =================
    const float b3v = __ldg(b3);
    #pragma unroll
    for (int r = 0; r < R; ++r) {
        ull a3 = pack2(b3v, 0.0f);
        #pragma unroll
        for (int v = 0; v < 4; ++v) {
            const ulonglong2 wv = *reinterpret_cast<const ulonglong2*>(W3S + 4 * v);
            a3 = ffma2(wv.x, pack2(h2[r][4 * v],     h2[r][4 * v + 1]), a3);
            a3 = ffma2(wv.y, pack2(h2[r][4 * v + 2], h2[r][4 * v + 3]), a3);
        }
        float lo, hi;
        unpack2(a3, lo, hi);
        int row = tid + THREADS * r;
        if (row < rows) out[r0 + row] = lo + hi;
    }
}

extern "C" void kernel_launch(void* const* d_in, const int* in_sizes, int n_in,
                              void* d_out, int out_size)
{
    const float* x_q      = (const float*)d_in[0];
    const float* x_c      = (const float*)d_in[1];
    const float* q_params = (const float*)d_in[2];
    const float* w1       = (const float*)d_in[3];
    const float* b1       = (const float*)d_in[4];
    const float* w2       = (const float*)d_in[5];
    const float* b2       = (const float*)d_in[6];
    const float* w3       = (const float*)d_in[7];
    const float* b3       = (const float*)d_in[8];
    float* out            = (float*)d_out;

    const int B = in_sizes[0] / 3;
    const int blocks = (B + TILE - 1) / TILE;

    cudaFuncSetAttribute(hybridq_kernel,
                         cudaFuncAttributeMaxDynamicSharedMemorySize, SMEM_BYTES);

    hybridq_kernel<<<blocks, THREADS, SMEM_BYTES>>>(
        x_q, x_c, q_params, w1, b1, w2, b2, w3, b3, out, B);
}